// round 6
// baseline (speedup 1.0000x reference)
#include <cuda_runtime.h>

#define KS   13
#define RAD  6
#define TW   32
#define TH   4            // block covers 32x4 outputs; 64 threads, 2 rows/thread
#define PW   (TW + 2*RAD) // 44
#define PH   (TH + 2*RAD) // 16
#define IMH  256
#define IMW  256
#define NC   4
#define NB   2
#define NT   64

__device__ __forceinline__ float fast_ex2(float x) {
    float r; asm("ex2.approx.ftz.f32 %0, %1;" : "=f"(r) : "f"(x)); return r;
}

// one row of 13 taps for a single center
__device__ __forceinline__ void row1(const float4* __restrict__ rp,
                                     const float* __restrict__ T,
                                     const float4 c, float& ws,
                                     float& aU01, float& aV01,
                                     float& aU23, float& aV23) {
    #pragma unroll
    for (int ix = 0; ix < KS; ix++) {
        float4 p = rp[ix];
        float m01 = fmaxf(fabsf(p.x - c.x), fabsf(p.y - c.y));
        float m23 = fmaxf(fabsf(p.z - c.z), fabsf(p.w - c.w));
        float d   = m01 + m23;
        float w   = fast_ex2(fmaf(d, -d, T[ix]));
        ws += w;
        aU01 = fmaf(w, p.x, aU01);
        aV01 = fmaf(w, p.y, aV01);
        aU23 = fmaf(w, p.z, aU23);
        aV23 = fmaf(w, p.w, aV23);
    }
}

// one row of 13 taps serving BOTH centers (single LDS per tap)
__device__ __forceinline__ void row2(const float4* __restrict__ rp,
                                     const float* __restrict__ T1,
                                     const float* __restrict__ T2,
                                     const float4 c1, const float4 c2,
                                     float& ws1, float& aU01a, float& aV01a,
                                     float& aU23a, float& aV23a,
                                     float& ws2, float& aU01b, float& aV01b,
                                     float& aU23b, float& aV23b) {
    #pragma unroll
    for (int ix = 0; ix < KS; ix++) {
        float4 p = rp[ix];
        {
            float m01 = fmaxf(fabsf(p.x - c1.x), fabsf(p.y - c1.y));
            float m23 = fmaxf(fabsf(p.z - c1.z), fabsf(p.w - c1.w));
            float d   = m01 + m23;
            float w   = fast_ex2(fmaf(d, -d, T1[ix]));
            ws1 += w;
            aU01a = fmaf(w, p.x, aU01a);
            aV01a = fmaf(w, p.y, aV01a);
            aU23a = fmaf(w, p.z, aU23a);
            aV23a = fmaf(w, p.w, aV23a);
        }
        {
            float m01 = fmaxf(fabsf(p.x - c2.x), fabsf(p.y - c2.y));
            float m23 = fmaxf(fabsf(p.z - c2.z), fabsf(p.w - c2.w));
            float d   = m01 + m23;
            float w   = fast_ex2(fmaf(d, -d, T2[ix]));
            ws2 += w;
            aU01b = fmaf(w, p.x, aU01b);
            aV01b = fmaf(w, p.y, aV01b);
            aU23b = fmaf(w, p.z, aU23b);
            aV23b = fmaf(w, p.w, aV23b);
        }
    }
}

__global__ __launch_bounds__(NT, 12)
void bilateral13_v6(const float* __restrict__ x, float* __restrict__ out) {
    __shared__ float4 tile[PH][PW];   // sc * (u01, v01, u23, v23) basis
    __shared__ float  s_T[KS * KS];   // K2 * ((iy-6)^2 + (ix-6)^2)

    const int tid = threadIdx.x;      // 0..63
    const int b   = blockIdx.z;
    const int tx0 = blockIdx.x * TW;
    const int ty0 = blockIdx.y * TH;

    const float K2 = (-0.5f / 9.0f) * 1.4426950408889634f;
    const float SC = 0.28311592f;     // sqrt(-K2)

    // ---- spatial table ----
    for (int e = tid; e < KS * KS; e += NT) {
        const int iy = e / KS - RAD;
        const int ix = e % KS - RAD;
        s_T[e] = K2 * (float)(iy * iy + ix * ix);
    }

    // ---- cooperative load: reflect pad, (u,v) basis change, pre-scale -----
    const float* xb = x + (size_t)b * NC * IMH * IMW;
    #pragma unroll
    for (int it = 0; it < (PH * PW + NT - 1) / NT; it++) {
        int i = tid + it * NT;
        if (i < PH * PW) {
            int py = i / PW, px = i % PW;
            int gy = ty0 + py - RAD;
            int gx = tx0 + px - RAD;
            gy = (gy < 0) ? -gy : ((gy >= IMH) ? (2 * IMH - 2 - gy) : gy);
            gx = (gx < 0) ? -gx : ((gx >= IMW) ? (2 * IMW - 2 - gx) : gx);
            int g = gy * IMW + gx;
            float p0 = xb[0 * IMH * IMW + g];
            float p1 = xb[1 * IMH * IMW + g];
            float p2 = xb[2 * IMH * IMW + g];
            float p3 = xb[3 * IMH * IMW + g];
            float4 v;
            v.x = SC * (p0 + p1);
            v.y = SC * (p0 - p1);
            v.z = SC * (p2 + p3);
            v.w = SC * (p2 - p3);
            tile[py][px] = v;
        }
    }
    __syncthreads();

    // ---- per-thread: two vertically adjacent output pixels -----------------
    const int lx = tid & (TW - 1);    // 0..31
    const int ly = tid >> 5;          // 0..1  -> output rows 2ly, 2ly+1
    const int r0 = 2 * ly;            // first window row (tile coords)

    const float4 c1 = tile[r0 + RAD][lx + RAD];
    const float4 c2 = tile[r0 + RAD + 1][lx + RAD];

    float ws1 = 0.f, aU01a = 0.f, aV01a = 0.f, aU23a = 0.f, aV23a = 0.f;
    float ws2 = 0.f, aU01b = 0.f, aV01b = 0.f, aU23b = 0.f, aV23b = 0.f;

    // j = 0: center1 only (spatial row 0)
    row1(&tile[r0][lx], &s_T[0], c1, ws1, aU01a, aV01a, aU23a, aV23a);

    // j = 1..12: both centers share the row load
    #pragma unroll 1
    for (int j = 1; j <= 12; j++) {
        row2(&tile[r0 + j][lx], &s_T[j * KS], &s_T[(j - 1) * KS],
             c1, c2,
             ws1, aU01a, aV01a, aU23a, aV23a,
             ws2, aU01b, aV01b, aU23b, aV23b);
    }

    // j = 13: center2 only (spatial row 12)
    row1(&tile[r0 + 13][lx], &s_T[12 * KS], c2, ws2, aU01b, aV01b, aU23b, aV23b);

    // ---- epilogue: undo basis change + pre-scale, normalize ----
    float* ob = out + (size_t)b * NC * IMH * IMW;
    const int y1 = ty0 + 2 * ly;
    const int o1 = y1 * IMW + tx0 + lx;
    const int o2 = o1 + IMW;

    const float h1 = __fdividef(0.5f, SC * ws1);
    ob[0 * IMH * IMW + o1] = (aU01a + aV01a) * h1;
    ob[1 * IMH * IMW + o1] = (aU01a - aV01a) * h1;
    ob[2 * IMH * IMW + o1] = (aU23a + aV23a) * h1;
    ob[3 * IMH * IMW + o1] = (aU23a - aV23a) * h1;

    const float h2 = __fdividef(0.5f, SC * ws2);
    ob[0 * IMH * IMW + o2] = (aU01b + aV01b) * h2;
    ob[1 * IMH * IMW + o2] = (aU01b - aV01b) * h2;
    ob[2 * IMH * IMW + o2] = (aU23b + aV23b) * h2;
    ob[3 * IMH * IMW + o2] = (aU23b - aV23b) * h2;
}

extern "C" void kernel_launch(void* const* d_in, const int* in_sizes, int n_in,
                              void* d_out, int out_size) {
    const float* x = (const float*)d_in[0];
    float* out = (float*)d_out;
    dim3 grid(IMW / TW, IMH / TH, NB);   // 8 x 64 x 2 = 1024 blocks
    bilateral13_v6<<<grid, NT>>>(x, out);
}